// round 12
// baseline (speedup 1.0000x reference)
#include <cuda_runtime.h>
#include <cuda_bf16.h>

#define NF   13776
#define KC   8
#define NT   256
#define RPW  4                         // receivers per warp
#define RPB  32                        // receivers per block
#define NBLK ((NF + RPB - 1) / RPB)    // 431 blocks (last block: 16 valid receivers)

// ---------------- scratch (device globals; no allocs) ----------------
__device__ float4   g_lo[NF];          // AABB min; .w = face id0 (bits)
__device__ float4   g_hi[NF];          // AABB max; .w = face id1 (bits)
__device__ int      g_fc2[NF];         // face id2
__device__ float4   g_tri4[NF * 3];    // vertex k of face f at [f*3+k]
__device__ float    g_partial[NBLK];
__device__ unsigned g_done = 0;        // self-resetting ticket

__device__ __forceinline__ float min3(float a, float b, float c) { return fminf(a, fminf(b, c)); }
__device__ __forceinline__ float max3(float a, float b, float c) { return fmaxf(a, fmaxf(b, c)); }

// ---------------- kernel 1: build SoA AABBs + packed ids + triangles ----------------
__global__ void __launch_bounds__(256)
setup_kernel(const float* __restrict__ verts,
             const int*   __restrict__ faces) {
    int f = blockIdx.x * 256 + threadIdx.x;
    if (f >= NF) return;

    int i0 = faces[3 * f + 0];
    int i1 = faces[3 * f + 1];
    int i2 = faces[3 * f + 2];

    float ax = verts[3 * i0 + 0], ay = verts[3 * i0 + 1], az = verts[3 * i0 + 2];
    float bx = verts[3 * i1 + 0], by = verts[3 * i1 + 1], bz = verts[3 * i1 + 2];
    float cx = verts[3 * i2 + 0], cy = verts[3 * i2 + 1], cz = verts[3 * i2 + 2];

    g_tri4[f * 3 + 0] = make_float4(ax, ay, az, 0.0f);
    g_tri4[f * 3 + 1] = make_float4(bx, by, bz, 0.0f);
    g_tri4[f * 3 + 2] = make_float4(cx, cy, cz, 0.0f);

    g_lo[f] = make_float4(min3(ax, bx, cx), min3(ay, by, cy), min3(az, bz, cz),
                          __int_as_float(i0));
    g_hi[f] = make_float4(max3(ax, bx, cx), max3(ay, by, cy), max3(az, bz, cz),
                          __int_as_float(i1));
    g_fc2[f] = i2;
}

// ---------------- cone-field penalty (matches jnp fp32 math) ----------------
__device__ __forceinline__ float cone_pen(const float* __restrict__ s,
                                          const float* __restrict__ p) {
    float e0x = s[3] - s[0], e0y = s[4] - s[1], e0z = s[5] - s[2];
    float e1x = s[6] - s[0], e1y = s[7] - s[1], e1z = s[8] - s[2];
    float nx = e0y * e1z - e0z * e1y;
    float ny = e0z * e1x - e0x * e1z;
    float nz = e0x * e1y - e0y * e1x;
    float inv = 1.0f / (sqrtf(nx * nx + ny * ny + nz * nz) + 1e-8f);
    nx *= inv; ny *= inv; nz *= inv;
    float cx = (s[0] + s[3] + s[6]) * (1.0f / 3.0f);
    float cy = (s[1] + s[4] + s[7]) * (1.0f / 3.0f);
    float cz = (s[2] + s[5] + s[8]) * (1.0f / 3.0f);

    float acc = 0.0f;
#pragma unroll
    for (int v = 0; v < 3; ++v) {
        float ux = p[3 * v + 0] - cx;
        float uy = p[3 * v + 1] - cy;
        float uz = p[3 * v + 2] - cz;
        float h = ux * nx + uy * ny + uz * nz;
        float wx = ux - h * nx, wy = uy - h * ny, wz = uz - h * nz;
        float r = sqrtf(wx * wx + wy * wy + wz * wz);
        float radial = fmaxf(1.0f - 2.0f * r, 0.0f);
        float depth  = fmaxf(-h, 0.0f) + fmaxf(h, 0.0f) * __expf(-2.0f * h);
        float phi = radial * depth;
        acc += phi * phi;
    }
    return acc;
}

// ---------------- kernel 2: broad (AABB-only, 4 recv/warp) + verify + narrow + reduce ----------------
__global__ void __launch_bounds__(NT)
fused_kernel(float* __restrict__ out) {
    const int t    = threadIdx.x;
    const int lane = t & 31;
    const int w    = t >> 5;
    const int blockBase = blockIdx.x * RPB;
    const int iBase = blockBase + RPW * w;        // first receiver of this warp

    __shared__ int   sPairs[RPB][KC];
    __shared__ float ssum[NT / 32];
    __shared__ bool  sLast;

    // ---- receiver AABBs (broadcast loads); invalid receivers start "complete" ----
    float4 rlo[RPW], rhi[RPW];
    int cnt0, cnt1, cnt2, cnt3;
#pragma unroll
    for (int r = 0; r < RPW; ++r) {
        int i = iBase + r;
        if (i < NF) { rlo[r] = g_lo[i]; rhi[r] = g_hi[i]; }
        else {
            rlo[r] = make_float4( 1e30f,  1e30f,  1e30f, 0.0f);
            rhi[r] = make_float4(-1e30f, -1e30f, -1e30f, 0.0f);
        }
    }
    cnt0 = (iBase + 0 < NF) ? 0 : KC;
    cnt1 = (iBase + 1 < NF) ? 0 : KC;
    cnt2 = (iBase + 2 < NF) ? 0 : KC;
    cnt3 = (iBase + 3 < NF) ? 0 : KC;

    // ---- broad phase: AABB-only predicate, 4 ballot streams per load ----
    for (int base = 0;
         base < NF && ((cnt0 < KC) | (cnt1 < KC) | (cnt2 < KC) | (cnt3 < KC));
         base += 32) {
        int j = base + lane;
        bool inb = (j < NF);
        float4 jlo, jhi;
        if (inb) { jlo = g_lo[j]; jhi = g_hi[j]; }
        unsigned lt = (1u << lane) - 1u;

#define BROAD_STEP(R, CNT)                                                      \
        {                                                                       \
            bool ok = inb &&                                                    \
                (rlo[R].x <= jhi.x) & (jlo.x <= rhi[R].x) &                     \
                (rlo[R].y <= jhi.y) & (jlo.y <= rhi[R].y) &                     \
                (rlo[R].z <= jhi.z) & (jlo.z <= rhi[R].z);                      \
            unsigned m = __ballot_sync(0xffffffffu, ok);                        \
            int rk = __popc(m & lt);                                            \
            if (ok && (CNT + rk) < KC) sPairs[RPW * w + R][CNT + rk] = j;       \
            CNT = min(KC, CNT + __popc(m));                                     \
        }
        BROAD_STEP(0, cnt0)
        BROAD_STEP(1, cnt1)
        BROAD_STEP(2, cnt2)
        BROAD_STEP(3, cnt3)
#undef BROAD_STEP
    }
    if (lane < KC) {
        if (lane >= cnt0) sPairs[RPW * w + 0][lane] = -1;
        if (lane >= cnt1) sPairs[RPW * w + 1][lane] = -1;
        if (lane >= cnt2) sPairs[RPW * w + 2][lane] = -1;
        if (lane >= cnt3) sPairs[RPW * w + 3][lane] = -1;
    }
    __syncwarp();

    // ---- verify: lane = r*8+k checks collected pair for shared vertices ----
    {
        int r = lane >> 3;           // 0..3
        int k = lane & 7;
        int i = iBase + r;
        bool shared = false;
        if (i < NF) {
            int j = sPairs[RPW * w + r][k];
            if (j >= 0) {
                int i0 = __float_as_int(rlo[r].w);
                int i1 = __float_as_int(rhi[r].w);
                int i2 = g_fc2[i];
                int j0 = __float_as_int(g_lo[j].w);
                int j1 = __float_as_int(g_hi[j].w);
                int j2 = g_fc2[j];
                shared = (i0 == j0) | (i0 == j1) | (i0 == j2) |
                         (i1 == j0) | (i1 == j1) | (i1 == j2) |
                         (i2 == j0) | (i2 == j1) | (i2 == j2);
            }
        }
        unsigned redo = __ballot_sync(0xffffffffu, shared);

        // rare: exact rescan (AABB + share) for flagged receivers
        if (redo) {
#pragma unroll
            for (int r2 = 0; r2 < RPW; ++r2) {
                if ((redo >> (8 * r2)) & 0xFFu) {
                    int i2g = iBase + r2;
                    int ri0 = __float_as_int(rlo[r2].w);
                    int ri1 = __float_as_int(rhi[r2].w);
                    int ri2 = g_fc2[i2g];
                    int cnt = 0;
                    for (int base = 0; base < NF && cnt < KC; base += 32) {
                        int j = base + lane;
                        bool ok = false;
                        if (j < NF) {
                            float4 jlo = g_lo[j];
                            float4 jhi = g_hi[j];
                            ok = (rlo[r2].x <= jhi.x) & (jlo.x <= rhi[r2].x) &
                                 (rlo[r2].y <= jhi.y) & (jlo.y <= rhi[r2].y) &
                                 (rlo[r2].z <= jhi.z) & (jlo.z <= rhi[r2].z);
                            if (ok) {
                                int j0 = __float_as_int(jlo.w);
                                int j1 = __float_as_int(jhi.w);
                                int j2 = g_fc2[j];
                                bool sh = (ri0 == j0) | (ri0 == j1) | (ri0 == j2) |
                                          (ri1 == j0) | (ri1 == j1) | (ri1 == j2) |
                                          (ri2 == j0) | (ri2 == j1) | (ri2 == j2);
                                ok = !sh;
                            }
                        }
                        unsigned m = __ballot_sync(0xffffffffu, ok);
                        int rk = __popc(m & ((1u << lane) - 1u));
                        if (ok && (cnt + rk) < KC) sPairs[RPW * w + r2][cnt + rk] = j;
                        cnt = min(KC, cnt + __popc(m));
                    }
                    if (lane < KC && lane >= cnt) sPairs[RPW * w + r2][lane] = -1;
                }
            }
        }
    }
    __syncthreads();

    // ---- narrow phase: thread t -> (r = t>>3, k = t&7), BOTH directions ----
    float acc = 0.0f;
    {
        int r = t >> 3;              // 0..31
        int k = t & 7;
        int i = blockBase + r;
        if (i < NF) {
            int j = sPairs[r][k];
            if (j >= 0) {
                float a[9], b[9];
                float4 v0 = g_tri4[i * 3 + 0], v1 = g_tri4[i * 3 + 1], v2 = g_tri4[i * 3 + 2];
                a[0] = v0.x; a[1] = v0.y; a[2] = v0.z;
                a[3] = v1.x; a[4] = v1.y; a[5] = v1.z;
                a[6] = v2.x; a[7] = v2.y; a[8] = v2.z;
                float4 u0 = g_tri4[j * 3 + 0], u1 = g_tri4[j * 3 + 1], u2 = g_tri4[j * 3 + 2];
                b[0] = u0.x; b[1] = u0.y; b[2] = u0.z;
                b[3] = u1.x; b[4] = u1.y; b[5] = u1.z;
                b[6] = u2.x; b[7] = u2.y; b[8] = u2.z;
                acc = cone_pen(a, b) + cone_pen(b, a);
            }
        }
    }

    // ---- block reduce (fixed order) ----
#pragma unroll
    for (int off = 16; off > 0; off >>= 1)
        acc += __shfl_down_sync(0xffffffffu, acc, off);
    if (lane == 0) ssum[w] = acc;
    __syncthreads();
    if (t == 0) {
        float v = 0.0f;
#pragma unroll
        for (int q = 0; q < NT / 32; ++q) v += ssum[q];
        g_partial[blockIdx.x] = v;
        __threadfence();
        unsigned ticket = atomicAdd(&g_done, 1);
        bool last = (ticket == NBLK - 1);
        if (last) g_done = 0;                    // reset for next graph replay
        sLast = last;
    }
    __syncthreads();

    // ---- last finishing block: fixed-order final sum ----
    if (sLast) {
        float a = 0.0f;
        for (int b = t; b < NBLK; b += NT)
            a += g_partial[b];
#pragma unroll
        for (int off = 16; off > 0; off >>= 1)
            a += __shfl_down_sync(0xffffffffu, a, off);
        __shared__ float fsum[NT / 32];
        if (lane == 0) fsum[w] = a;
        __syncthreads();
        if (t == 0) {
            float v = 0.0f;
#pragma unroll
            for (int q = 0; q < NT / 32; ++q) v += fsum[q];
            out[0] = v;
        }
    }
}

// ---------------- launch ----------------
extern "C" void kernel_launch(void* const* d_in, const int* in_sizes, int n_in,
                              void* d_out, int out_size) {
    const float* verts = (const float*)d_in[0];
    const int*   faces = (const int*)d_in[1];
    float* out = (float*)d_out;

    setup_kernel<<<(NF + 255) / 256, 256>>>(verts, faces);
    fused_kernel<<<NBLK, NT>>>(out);
}

// round 13
// speedup vs baseline: 1.2694x; 1.2694x over previous
#include <cuda_runtime.h>
#include <cuda_bf16.h>

#define NF   13776
#define KC   8
#define NT   256
#define RPB  16                   // receivers per block (2 per warp)
#define NBLK (NF / RPB)           // 861 blocks, exact
#define T1J  128                  // faces staged in smem; top-8 ~always inside

// ---------------- scratch (device globals; no allocs) ----------------
__device__ float    g_partial[NBLK];
__device__ unsigned g_done = 0;   // self-resetting ticket

__device__ __forceinline__ float min3(float a, float b, float c) { return fminf(a, fminf(b, c)); }
__device__ __forceinline__ float max3(float a, float b, float c) { return fmaxf(a, fmaxf(b, c)); }

// ---------------- cone-field penalty (matches jnp fp32 math) ----------------
// SIGMA=0.5 -> r/SIGMA=2r, h/SIGMA=2h. POINT2PLANE=False, PENALIZE_OUTSIDE=True.
__device__ __forceinline__ float cone_pen(const float* __restrict__ s,
                                          const float* __restrict__ p) {
    float e0x = s[3] - s[0], e0y = s[4] - s[1], e0z = s[5] - s[2];
    float e1x = s[6] - s[0], e1y = s[7] - s[1], e1z = s[8] - s[2];
    float nx = e0y * e1z - e0z * e1y;
    float ny = e0z * e1x - e0x * e1z;
    float nz = e0x * e1y - e0y * e1x;
    float inv = 1.0f / (sqrtf(nx * nx + ny * ny + nz * nz) + 1e-8f);
    nx *= inv; ny *= inv; nz *= inv;
    float cx = (s[0] + s[3] + s[6]) * (1.0f / 3.0f);
    float cy = (s[1] + s[4] + s[7]) * (1.0f / 3.0f);
    float cz = (s[2] + s[5] + s[8]) * (1.0f / 3.0f);

    float acc = 0.0f;
#pragma unroll
    for (int v = 0; v < 3; ++v) {
        float ux = p[3 * v + 0] - cx;
        float uy = p[3 * v + 1] - cy;
        float uz = p[3 * v + 2] - cz;
        float h = ux * nx + uy * ny + uz * nz;
        float wx = ux - h * nx, wy = uy - h * ny, wz = uz - h * nz;
        float r = sqrtf(wx * wx + wy * wy + wz * wz);
        float radial = fmaxf(1.0f - 2.0f * r, 0.0f);
        float depth  = fmaxf(-h, 0.0f) + fmaxf(h, 0.0f) * __expf(-2.0f * h);
        float phi = radial * depth;
        acc += phi * phi;
    }
    return acc;
}

// ---------------- single fused kernel ----------------
__global__ void __launch_bounds__(NT)
fused_kernel(const float* __restrict__ verts,
             const int*   __restrict__ faces,
             float* __restrict__ out) {
    const int t    = threadIdx.x;
    const int lane = t & 31;
    const int w    = t >> 5;
    const int blockBase = blockIdx.x * RPB;

    __shared__ float4 sLo[T1J], sHi[T1J];       // .w = id0 / id1 (bits)
    __shared__ int    sId2[T1J];
    __shared__ float4 sTri[T1J][3];
    __shared__ float4 sRlo[RPB], sRhi[RPB];     // .w = id0 / id1 (bits)
    __shared__ int    sRid2[RPB];
    __shared__ float4 sRtri[RPB][3];
    __shared__ int    sPairs[RPB][KC];
    __shared__ float  ssum[NT / 32];
    __shared__ bool   sLast;

    // ---- prologue: stage chunk faces [0,T1J) + this block's receivers ----
    if (t < T1J) {
        int f = t;
        int i0 = faces[3 * f + 0], i1 = faces[3 * f + 1], i2 = faces[3 * f + 2];
        float ax = verts[3 * i0 + 0], ay = verts[3 * i0 + 1], az = verts[3 * i0 + 2];
        float bx = verts[3 * i1 + 0], by = verts[3 * i1 + 1], bz = verts[3 * i1 + 2];
        float cx = verts[3 * i2 + 0], cy = verts[3 * i2 + 1], cz = verts[3 * i2 + 2];
        sTri[f][0] = make_float4(ax, ay, az, 0.0f);
        sTri[f][1] = make_float4(bx, by, bz, 0.0f);
        sTri[f][2] = make_float4(cx, cy, cz, 0.0f);
        sLo[f] = make_float4(min3(ax, bx, cx), min3(ay, by, cy), min3(az, bz, cz),
                             __int_as_float(i0));
        sHi[f] = make_float4(max3(ax, bx, cx), max3(ay, by, cy), max3(az, bz, cz),
                             __int_as_float(i1));
        sId2[f] = i2;
    } else if (t < T1J + RPB) {
        int r = t - T1J;
        int f = blockBase + r;
        int i0 = faces[3 * f + 0], i1 = faces[3 * f + 1], i2 = faces[3 * f + 2];
        float ax = verts[3 * i0 + 0], ay = verts[3 * i0 + 1], az = verts[3 * i0 + 2];
        float bx = verts[3 * i1 + 0], by = verts[3 * i1 + 1], bz = verts[3 * i1 + 2];
        float cx = verts[3 * i2 + 0], cy = verts[3 * i2 + 1], cz = verts[3 * i2 + 2];
        sRtri[r][0] = make_float4(ax, ay, az, 0.0f);
        sRtri[r][1] = make_float4(bx, by, bz, 0.0f);
        sRtri[r][2] = make_float4(cx, cy, cz, 0.0f);
        sRlo[r] = make_float4(min3(ax, bx, cx), min3(ay, by, cy), min3(az, bz, cz),
                              __int_as_float(i0));
        sRhi[r] = make_float4(max3(ax, bx, cx), max3(ay, by, cy), max3(az, bz, cz),
                              __int_as_float(i1));
        sRid2[r] = i2;
    }
    __syncthreads();

    // ---- broad phase: warp ballot scan over smem, 2 receivers/warp ----
    const int rA = 2 * w, rB = 2 * w + 1;
    float4 rloA = sRlo[rA], rhiA = sRhi[rA];
    float4 rloB = sRlo[rB], rhiB = sRhi[rB];
    int a0 = __float_as_int(rloA.w), a1 = __float_as_int(rhiA.w), a2 = sRid2[rA];
    int b0 = __float_as_int(rloB.w), b1 = __float_as_int(rhiB.w), b2 = sRid2[rB];

    int cntA = 0, cntB = 0;
    for (int base = 0; base < T1J && (cntA < KC || cntB < KC); base += 32) {
        int j = base + lane;
        float4 jlo = sLo[j];
        float4 jhi = sHi[j];
        int j0 = __float_as_int(jlo.w);
        int j1 = __float_as_int(jhi.w);
        int j2 = sId2[j];

        bool okA = (rloA.x <= jhi.x) & (jlo.x <= rhiA.x) &
                   (rloA.y <= jhi.y) & (jlo.y <= rhiA.y) &
                   (rloA.z <= jhi.z) & (jlo.z <= rhiA.z);
        bool okB = (rloB.x <= jhi.x) & (jlo.x <= rhiB.x) &
                   (rloB.y <= jhi.y) & (jlo.y <= rhiB.y) &
                   (rloB.z <= jhi.z) & (jlo.z <= rhiB.z);
        if (okA) {
            bool sh = (a0 == j0) | (a0 == j1) | (a0 == j2) |
                      (a1 == j0) | (a1 == j1) | (a1 == j2) |
                      (a2 == j0) | (a2 == j1) | (a2 == j2);
            okA = !sh;
        }
        if (okB) {
            bool sh = (b0 == j0) | (b0 == j1) | (b0 == j2) |
                      (b1 == j0) | (b1 == j1) | (b1 == j2) |
                      (b2 == j0) | (b2 == j1) | (b2 == j2);
            okB = !sh;
        }
        unsigned mA = __ballot_sync(0xffffffffu, okA);
        unsigned mB = __ballot_sync(0xffffffffu, okB);
        unsigned lt = (1u << lane) - 1u;
        int rkA = __popc(mA & lt);
        int rkB = __popc(mB & lt);
        if (okA && (cntA + rkA) < KC) sPairs[rA][cntA + rkA] = j;
        if (okB && (cntB + rkB) < KC) sPairs[rB][cntB + rkB] = j;
        cntA = min(KC, cntA + __popc(mA));
        cntB = min(KC, cntB + __popc(mB));
    }

    // ---- exactness fallback (statistically ~never): continue into global ----
    if (cntA < KC || cntB < KC) {
#pragma unroll
        for (int sel = 0; sel < 2; ++sel) {
            int  rr  = sel ? rB : rA;
            int  cnt = sel ? cntB : cntA;
            if (cnt >= KC) continue;
            float4 rlo = sel ? rloB : rloA;
            float4 rhi = sel ? rhiB : rhiA;
            int q0 = sel ? b0 : a0, q1 = sel ? b1 : a1, q2 = sel ? b2 : a2;
            for (int base = T1J; base < NF && cnt < KC; base += 32) {
                int j = base + lane;
                bool ok = false;
                if (j < NF) {
                    int j0 = faces[3 * j + 0], j1 = faces[3 * j + 1], j2 = faces[3 * j + 2];
                    float ax = verts[3 * j0 + 0], ay = verts[3 * j0 + 1], az = verts[3 * j0 + 2];
                    float bx = verts[3 * j1 + 0], by = verts[3 * j1 + 1], bz = verts[3 * j1 + 2];
                    float cx = verts[3 * j2 + 0], cy = verts[3 * j2 + 1], cz = verts[3 * j2 + 2];
                    float jlx = min3(ax, bx, cx), jhx = max3(ax, bx, cx);
                    float jly = min3(ay, by, cy), jhy = max3(ay, by, cy);
                    float jlz = min3(az, bz, cz), jhz = max3(az, bz, cz);
                    ok = (rlo.x <= jhx) & (jlx <= rhi.x) &
                         (rlo.y <= jhy) & (jly <= rhi.y) &
                         (rlo.z <= jhz) & (jlz <= rhi.z);
                    if (ok) {
                        bool sh = (q0 == j0) | (q0 == j1) | (q0 == j2) |
                                  (q1 == j0) | (q1 == j1) | (q1 == j2) |
                                  (q2 == j0) | (q2 == j1) | (q2 == j2);
                        ok = !sh;
                    }
                }
                unsigned m = __ballot_sync(0xffffffffu, ok);
                int rk = __popc(m & ((1u << lane) - 1u));
                if (ok && (cnt + rk) < KC) sPairs[rr][cnt + rk] = j;
                cnt = min(KC, cnt + __popc(m));
            }
            if (sel) cntB = cnt; else cntA = cnt;
        }
    }

    if (lane < KC) {
        if (lane >= cntA) sPairs[rA][lane] = -1;
        if (lane >= cntB) sPairs[rB][lane] = -1;
    }
    __syncthreads();

    // ---- narrow phase: 256 tasks (r = t>>4, k = (t>>1)&7, dir = t&1) ----
    float acc = 0.0f;
    {
        int r = t >> 4;
        int k = (t >> 1) & 7;
        int j = sPairs[r][k];
        if (j >= 0) {
            float a[9], b[9];
            float4 v0 = sRtri[r][0], v1 = sRtri[r][1], v2 = sRtri[r][2];
            a[0] = v0.x; a[1] = v0.y; a[2] = v0.z;
            a[3] = v1.x; a[4] = v1.y; a[5] = v1.z;
            a[6] = v2.x; a[7] = v2.y; a[8] = v2.z;
            if (j < T1J) {
                float4 u0 = sTri[j][0], u1 = sTri[j][1], u2 = sTri[j][2];
                b[0] = u0.x; b[1] = u0.y; b[2] = u0.z;
                b[3] = u1.x; b[4] = u1.y; b[5] = u1.z;
                b[6] = u2.x; b[7] = u2.y; b[8] = u2.z;
            } else {  // fallback-found pair (rare): gather from global
                int j0 = faces[3 * j + 0], j1 = faces[3 * j + 1], j2 = faces[3 * j + 2];
                b[0] = verts[3 * j0 + 0]; b[1] = verts[3 * j0 + 1]; b[2] = verts[3 * j0 + 2];
                b[3] = verts[3 * j1 + 0]; b[4] = verts[3 * j1 + 1]; b[5] = verts[3 * j1 + 2];
                b[6] = verts[3 * j2 + 0]; b[7] = verts[3 * j2 + 1]; b[8] = verts[3 * j2 + 2];
            }
            acc = (t & 1) ? cone_pen(b, a) : cone_pen(a, b);
        }
    }

    // ---- block reduce (fixed order) ----
#pragma unroll
    for (int off = 16; off > 0; off >>= 1)
        acc += __shfl_down_sync(0xffffffffu, acc, off);
    if (lane == 0) ssum[w] = acc;
    __syncthreads();
    if (t == 0) {
        float v = 0.0f;
#pragma unroll
        for (int q = 0; q < NT / 32; ++q) v += ssum[q];
        g_partial[blockIdx.x] = v;
        __threadfence();
        unsigned ticket = atomicAdd(&g_done, 1);
        bool last = (ticket == NBLK - 1);
        if (last) g_done = 0;                    // reset for next graph replay
        sLast = last;
    }
    __syncthreads();

    // ---- last finishing block: fixed-order final sum ----
    if (sLast) {
        float a = 0.0f;
        for (int b = t; b < NBLK; b += NT)
            a += g_partial[b];
#pragma unroll
        for (int off = 16; off > 0; off >>= 1)
            a += __shfl_down_sync(0xffffffffu, a, off);
        __shared__ float fsum[NT / 32];
        if (lane == 0) fsum[w] = a;
        __syncthreads();
        if (t == 0) {
            float v = 0.0f;
#pragma unroll
            for (int q = 0; q < NT / 32; ++q) v += fsum[q];
            out[0] = v;
        }
    }
}

// ---------------- launch ----------------
extern "C" void kernel_launch(void* const* d_in, const int* in_sizes, int n_in,
                              void* d_out, int out_size) {
    const float* verts = (const float*)d_in[0];
    const int*   faces = (const int*)d_in[1];
    float* out = (float*)d_out;

    fused_kernel<<<NBLK, NT>>>(verts, faces, out);
}